// round 11
// baseline (speedup 1.0000x reference)
#include <cuda_runtime.h>
#include <cuda_fp16.h>

#define N_NODES 100000
#define N_EDGES 1600000
#define HID 128
#define C_OUT 64
#define NB_SCAN 98   // ceil(100000/1024)
#define XSPAD 132    // 128 + 4 pad, keeps 16B alignment
#define SMEM_GEMM (128 * XSPAD * 4)  // 67584 B dynamic smem

// ---- scratch (__device__ globals; allocation-free rule) ----
__device__ __align__(16) float g_dis[N_NODES];
__device__ int   g_cnt[N_NODES];
__device__ int   g_cursor[N_NODES];
__device__ int   g_incl[N_NODES];
__device__ int   g_part[128];
__device__ int   g_partx[128];
__device__ int   g_row_start[N_NODES + 1];
__device__ int   g_csr_src[N_EDGES];
__device__ __align__(16) __half g_G[(size_t)N_NODES * HID];  // dis * (x@W1) (fp16)
__device__ __align__(16) __half g_H[(size_t)N_NODES * HID];  // dis * h      (fp16)
__device__ __align__(16) __half g_A[(size_t)N_NODES * HID];  // ah           (fp16)

// ---------- f32x2 helpers ----------
#define FMA2(d, a, b) asm("fma.rn.f32x2 %0, %1, %2, %0;" : "+l"(d) : "l"(a), "l"(b))
#define PACK_BB(d, f) asm("mov.b64 %0, {%1, %1};" : "=l"(d) : "f"(f))
#define UNPACK2(lo, hi, d) asm("mov.b64 {%0, %1}, %2;" : "=f"(lo), "=f"(hi) : "l"(d))

// ---------------- degree / CSR build ----------------
__global__ void k_zero_cnt() {
    int i = blockIdx.x * blockDim.x + threadIdx.x;
    if (i < N_NODES) g_cnt[i] = 0;
}

__global__ void k_hist(const int* __restrict__ ei) {
    int e = blockIdx.x * blockDim.x + threadIdx.x;
    if (e < N_EDGES) {
        unsigned d = (unsigned)ei[N_EDGES + e];
        if (d < N_NODES) atomicAdd(&g_cnt[d], 1);
    }
}

__global__ void k_dis() {
    int i = blockIdx.x * blockDim.x + threadIdx.x;
    if (i < N_NODES) g_dis[i] = rsqrtf((float)g_cnt[i] + 1.0f);
}

__global__ void k_scan1() {
    __shared__ int sm[1024];
    int i = blockIdx.x * 1024 + threadIdx.x;
    sm[threadIdx.x] = (i < N_NODES) ? g_cnt[i] : 0;
    __syncthreads();
#pragma unroll
    for (int off = 1; off < 1024; off <<= 1) {
        int t = (threadIdx.x >= off) ? sm[threadIdx.x - off] : 0;
        __syncthreads();
        sm[threadIdx.x] += t;
        __syncthreads();
    }
    if (i < N_NODES) g_incl[i] = sm[threadIdx.x];
    if (threadIdx.x == 1023) g_part[blockIdx.x] = sm[1023];
}

__global__ void k_scan2() {
    __shared__ int sm[128];
    int t = threadIdx.x;
    int v = (t < NB_SCAN) ? g_part[t] : 0;
    sm[t] = v;
    __syncthreads();
#pragma unroll
    for (int off = 1; off < 128; off <<= 1) {
        int u = (t >= off) ? sm[t - off] : 0;
        __syncthreads();
        sm[t] += u;
        __syncthreads();
    }
    g_partx[t] = sm[t] - v;  // exclusive
}

__global__ void k_scan3() {
    int i = blockIdx.x * blockDim.x + threadIdx.x;
    if (i < N_NODES) {
        int rs = g_incl[i] - g_cnt[i] + g_partx[i >> 10];
        g_row_start[i] = rs;
        g_cursor[i] = rs;
    }
    if (i == 0) g_row_start[N_NODES] = N_EDGES;
}

__global__ void k_fill(const int* __restrict__ ei) {
    int e = blockIdx.x * blockDim.x + threadIdx.x;
    if (e < N_EDGES) {
        unsigned s = (unsigned)ei[e];
        unsigned d = (unsigned)ei[N_EDGES + e];
        if (s < N_NODES && d < N_NODES) {
            int pos = atomicAdd(&g_cursor[d], 1);
            g_csr_src[pos] = s;
        }
    }
}

// ---------------- GEMM1: G = fp16(dis * (X @ W1)), 128-row blocks ----------
// Warp ty owns 16 rows (8 row-pairs) x 128 cols. Per k per warp:
// 4 broadcast LDS.128 (x row-pairs) + 1 LDG.128 (W) = 8 wavefronts / 32 FMA2.
__global__ void __launch_bounds__(256) k_gemm1(const float* __restrict__ X,
                                               const float* __restrict__ W) {
    extern __shared__ float xsT_raw[];
    float (*xsT)[XSPAD] = (float (*)[XSPAD])xsT_raw;  // [k][row]
    const int tid = threadIdx.x;
    const int row0 = blockIdx.x * 128;

    {   // load + transpose X tile [128 x 128]
        int row = tid >> 1, seg = tid & 1;
        int gr = row0 + row;
        if (gr < N_NODES) {
            const float4* xr = (const float4*)(X + (size_t)gr * 128 + seg * 64);
#pragma unroll
            for (int i = 0; i < 16; i++) {
                float4 v = xr[i];
                int c = seg * 64 + i * 4;
                xsT[c + 0][row] = v.x; xsT[c + 1][row] = v.y;
                xsT[c + 2][row] = v.z; xsT[c + 3][row] = v.w;
            }
        } else {
#pragma unroll
            for (int i = 0; i < 16; i++) {
                int c = seg * 64 + i * 4;
                xsT[c + 0][row] = 0.f; xsT[c + 1][row] = 0.f;
                xsT[c + 2][row] = 0.f; xsT[c + 3][row] = 0.f;
            }
        }
    }
    __syncthreads();

    const int ty = tid >> 5, lane = tid & 31, col = lane * 4;
    const int rb = ty * 16;

    unsigned long long acc[8][4];  // [row-pair][col]
#pragma unroll
    for (int i = 0; i < 8; i++)
#pragma unroll
        for (int j = 0; j < 4; j++) acc[i][j] = 0ULL;

    for (int k = 0; k < 128; k++) {
        ulonglong2 xa = *(const ulonglong2*)&xsT[k][rb];       // rows 0-3
        ulonglong2 xb = *(const ulonglong2*)&xsT[k][rb + 4];   // rows 4-7
        ulonglong2 xc = *(const ulonglong2*)&xsT[k][rb + 8];   // rows 8-11
        ulonglong2 xd = *(const ulonglong2*)&xsT[k][rb + 12];  // rows 12-15
        float4 wv = *(const float4*)(W + (size_t)k * 128 + col);
        unsigned long long w0, w1, w2, w3;
        PACK_BB(w0, wv.x); PACK_BB(w1, wv.y); PACK_BB(w2, wv.z); PACK_BB(w3, wv.w);
        unsigned long long xr[8] = {xa.x, xa.y, xb.x, xb.y, xc.x, xc.y, xd.x, xd.y};
#pragma unroll
        for (int i = 0; i < 8; i++) {
            FMA2(acc[i][0], xr[i], w0);
            FMA2(acc[i][1], xr[i], w1);
            FMA2(acc[i][2], xr[i], w2);
            FMA2(acc[i][3], xr[i], w3);
        }
    }

#pragma unroll
    for (int rp = 0; rp < 8; rp++) {
        float lo0, hi0, lo1, hi1, lo2, hi2, lo3, hi3;
        UNPACK2(lo0, hi0, acc[rp][0]); UNPACK2(lo1, hi1, acc[rp][1]);
        UNPACK2(lo2, hi2, acc[rp][2]); UNPACK2(lo3, hi3, acc[rp][3]);
        int r0 = row0 + rb + rp * 2;
        if (r0 < N_NODES) {
            float dv = g_dis[r0];
            uint2 p;
            *(__half2*)&p.x = __floats2half2_rn(lo0 * dv, lo1 * dv);
            *(__half2*)&p.y = __floats2half2_rn(lo2 * dv, lo3 * dv);
            *(uint2*)(g_G + (size_t)r0 * 128 + col) = p;
        }
        int r1 = r0 + 1;
        if (r1 < N_NODES) {
            float dv = g_dis[r1];
            uint2 p;
            *(__half2*)&p.x = __floats2half2_rn(hi0 * dv, hi1 * dv);
            *(__half2*)&p.y = __floats2half2_rn(hi2 * dv, hi3 * dv);
            *(uint2*)(g_G + (size_t)r1 * 128 + col) = p;
        }
    }
}

// ---- weight-free gather: acc = F[w] + sum_j F[src_j], feats lane*4..+3 ----
__device__ __forceinline__ float4 gather_node(const __half* __restrict__ fin,
                                              int w, int lane) {
    const int fo = lane * 4;
    int start = g_row_start[w];
    int end   = g_row_start[w + 1];

    uint2 sp = *(const uint2*)(fin + (size_t)w * 128 + fo);
    float2 s01 = __half22float2(*(__half2*)&sp.x);
    float2 s23 = __half22float2(*(__half2*)&sp.y);
    float4 acc = make_float4(s01.x, s01.y, s23.x, s23.y);

    int j = start;
    for (; j + 4 <= end; j += 4) {
        int s0 = g_csr_src[j + 0], s1 = g_csr_src[j + 1];
        int s2 = g_csr_src[j + 2], s3 = g_csr_src[j + 3];
        uint2 p0 = *(const uint2*)(fin + (size_t)s0 * 128 + fo);
        uint2 p1 = *(const uint2*)(fin + (size_t)s1 * 128 + fo);
        uint2 p2 = *(const uint2*)(fin + (size_t)s2 * 128 + fo);
        uint2 p3 = *(const uint2*)(fin + (size_t)s3 * 128 + fo);
        {
            float2 a = __half22float2(*(__half2*)&p0.x), b = __half22float2(*(__half2*)&p0.y);
            acc.x += a.x; acc.y += a.y; acc.z += b.x; acc.w += b.y;
        }
        {
            float2 a = __half22float2(*(__half2*)&p1.x), b = __half22float2(*(__half2*)&p1.y);
            acc.x += a.x; acc.y += a.y; acc.z += b.x; acc.w += b.y;
        }
        {
            float2 a = __half22float2(*(__half2*)&p2.x), b = __half22float2(*(__half2*)&p2.y);
            acc.x += a.x; acc.y += a.y; acc.z += b.x; acc.w += b.y;
        }
        {
            float2 a = __half22float2(*(__half2*)&p3.x), b = __half22float2(*(__half2*)&p3.y);
            acc.x += a.x; acc.y += a.y; acc.z += b.x; acc.w += b.y;
        }
    }
    for (; j < end; j++) {
        int s = g_csr_src[j];
        uint2 p = *(const uint2*)(fin + (size_t)s * 128 + fo);
        float2 a = __half22float2(*(__half2*)&p.x), b = __half22float2(*(__half2*)&p.y);
        acc.x += a.x; acc.y += a.y; acc.z += b.x; acc.w += b.y;
    }
    return acc;
}

// PASS 0: H = fp16( dis_w * (b1 + dis_w * acc_G) )
// PASS 1: A = fp16( dis_w * acc_H )
template <int PASS>
__global__ void __launch_bounds__(256) k_gather(const float* __restrict__ b1) {
    int w = (blockIdx.x * 256 + threadIdx.x) >> 5;
    if (w >= N_NODES) return;
    int lane = threadIdx.x & 31;
    const int fo = lane * 4;
    float disd = g_dis[w];

    float4 acc = gather_node((PASS == 0) ? g_G : g_H, w, lane);
    uint2 p;
    if (PASS == 0) {
        float4 bv = *(const float4*)(b1 + fo);
        float h0 = disd * (bv.x + disd * acc.x);
        float h1 = disd * (bv.y + disd * acc.y);
        float h2 = disd * (bv.z + disd * acc.z);
        float h3 = disd * (bv.w + disd * acc.w);
        *(__half2*)&p.x = __floats2half2_rn(h0, h1);
        *(__half2*)&p.y = __floats2half2_rn(h2, h3);
        *(uint2*)(g_H + (size_t)w * 128 + fo) = p;
    } else {
        *(__half2*)&p.x = __floats2half2_rn(disd * acc.x, disd * acc.y);
        *(__half2*)&p.y = __floats2half2_rn(disd * acc.z, disd * acc.w);
        *(uint2*)(g_A + (size_t)w * 128 + fo) = p;
    }
}

// ---------------- GEMM2 + epilogue: 128-row blocks, 16 rows/warp ----------
__global__ void __launch_bounds__(256) k_gemm2(const float* __restrict__ Wmu,
                                               const float* __restrict__ bmu,
                                               const float* __restrict__ Wls,
                                               const float* __restrict__ bls,
                                               const float* __restrict__ eps,
                                               float* __restrict__ out) {
    extern __shared__ float xsT_raw[];
    float (*xsT)[XSPAD] = (float (*)[XSPAD])xsT_raw;
    const int tid = threadIdx.x;
    const int row0 = blockIdx.x * 128;

    {   // load + transpose A tile [128 x 128] fp16 -> f32
        int row = tid >> 1, seg = tid & 1;
        int gr = row0 + row;
        if (gr < N_NODES) {
            const uint2* xr = (const uint2*)(g_A + (size_t)gr * 128 + seg * 64);
#pragma unroll
            for (int i = 0; i < 16; i++) {
                uint2 pv = xr[i];
                float2 a = __half22float2(*(__half2*)&pv.x);
                float2 b = __half22float2(*(__half2*)&pv.y);
                int c = seg * 64 + i * 4;
                xsT[c + 0][row] = a.x; xsT[c + 1][row] = a.y;
                xsT[c + 2][row] = b.x; xsT[c + 3][row] = b.y;
            }
        } else {
#pragma unroll
            for (int i = 0; i < 16; i++) {
                int c = seg * 64 + i * 4;
                xsT[c + 0][row] = 0.f; xsT[c + 1][row] = 0.f;
                xsT[c + 2][row] = 0.f; xsT[c + 3][row] = 0.f;
            }
        }
    }
    __syncthreads();

    const int ty = tid >> 5, lane = tid & 31, jc = lane * 2;
    const int rb = ty * 16;

    unsigned long long am[8][2], al[8][2];  // [row-pair][col]
#pragma unroll
    for (int i = 0; i < 8; i++) {
        am[i][0] = am[i][1] = 0ULL;
        al[i][0] = al[i][1] = 0ULL;
    }

    for (int k = 0; k < 128; k++) {
        ulonglong2 xa = *(const ulonglong2*)&xsT[k][rb];
        ulonglong2 xb = *(const ulonglong2*)&xsT[k][rb + 4];
        ulonglong2 xc = *(const ulonglong2*)&xsT[k][rb + 8];
        ulonglong2 xd = *(const ulonglong2*)&xsT[k][rb + 12];
        float2 wm = *(const float2*)(Wmu + (size_t)k * 64 + jc);
        float2 wl = *(const float2*)(Wls + (size_t)k * 64 + jc);
        unsigned long long wm0, wm1, wl0, wl1;
        PACK_BB(wm0, wm.x); PACK_BB(wm1, wm.y);
        PACK_BB(wl0, wl.x); PACK_BB(wl1, wl.y);
        unsigned long long xr[8] = {xa.x, xa.y, xb.x, xb.y, xc.x, xc.y, xd.x, xd.y};
#pragma unroll
        for (int i = 0; i < 8; i++) {
            FMA2(am[i][0], xr[i], wm0);
            FMA2(am[i][1], xr[i], wm1);
            FMA2(al[i][0], xr[i], wl0);
            FMA2(al[i][1], xr[i], wl1);
        }
    }

    const size_t NOUT = (size_t)N_NODES * C_OUT;
    float bm0 = bmu[jc], bm1 = bmu[jc + 1];
    float bl0 = bls[jc], bl1 = bls[jc + 1];
#pragma unroll
    for (int rp = 0; rp < 8; rp++) {
        float m0lo, m0hi, m1lo, m1hi, l0lo, l0hi, l1lo, l1hi;
        UNPACK2(m0lo, m0hi, am[rp][0]); UNPACK2(m1lo, m1hi, am[rp][1]);
        UNPACK2(l0lo, l0hi, al[rp][0]); UNPACK2(l1lo, l1hi, al[rp][1]);
#pragma unroll
        for (int half = 0; half < 2; half++) {
            int r = row0 + rb + rp * 2 + half;
            if (r >= N_NODES) continue;
            float mu0 = (half ? m0hi : m0lo) + bm0;
            float mu1 = (half ? m1hi : m1lo) + bm1;
            float ls0 = (half ? l0hi : l0lo) + bl0;
            float ls1 = (half ? l1hi : l1lo) + bl1;
            float2 ev = *(const float2*)(eps + (size_t)r * 64 + jc);
            float z0 = mu0 + ev.x * __expf(ls0);
            float z1 = mu1 + ev.y * __expf(ls1);
            size_t off = (size_t)r * 64 + jc;
            *(float2*)(out + off)            = make_float2(z0, z1);
            *(float2*)(out + NOUT + off)     = make_float2(mu0, mu1);
            *(float2*)(out + 2 * NOUT + off) = make_float2(ls0, ls1);
        }
    }
}

extern "C" void kernel_launch(void* const* d_in, const int* in_sizes, int n_in,
                              void* d_out, int out_size) {
    const float* x   = (const float*)d_in[0];
    const int*   ei  = (const int*)d_in[1];   // int32 (JAX demotes int64)
    const float* W1  = (const float*)d_in[2];
    const float* b1  = (const float*)d_in[3];
    const float* Wmu = (const float*)d_in[4];
    const float* bmu = (const float*)d_in[5];
    const float* Wls = (const float*)d_in[6];
    const float* bls = (const float*)d_in[7];
    const float* eps = (const float*)d_in[8];
    float* out       = (float*)d_out;
    (void)in_sizes; (void)n_in; (void)out_size;

    cudaFuncSetAttribute(k_gemm1, cudaFuncAttributeMaxDynamicSharedMemorySize, SMEM_GEMM);
    cudaFuncSetAttribute(k_gemm2, cudaFuncAttributeMaxDynamicSharedMemorySize, SMEM_GEMM);

    k_zero_cnt<<<(N_NODES + 255) / 256, 256>>>();                       // 0
    k_hist<<<(N_EDGES + 255) / 256, 256>>>(ei);                         // 1
    k_dis<<<(N_NODES + 255) / 256, 256>>>();                            // 2
    k_gemm1<<<(N_NODES + 127) / 128, 256, SMEM_GEMM>>>(x, W1);          // 3 <- profiled
    k_scan1<<<NB_SCAN, 1024>>>();                                       // 4
    k_scan2<<<1, 128>>>();                                              // 5
    k_scan3<<<(N_NODES + 255) / 256, 256>>>();                          // 6
    k_fill<<<(N_EDGES + 255) / 256, 256>>>(ei);                         // 7
    k_gather<0><<<(N_NODES + 7) / 8, 256>>>(b1);                        // 8
    k_gather<1><<<(N_NODES + 7) / 8, 256>>>(b1);                        // 9
    k_gemm2<<<(N_NODES + 127) / 128, 256, SMEM_GEMM>>>(Wmu, bmu, Wls, bls, eps, out);  // 10
}